// round 8
// baseline (speedup 1.0000x reference)
#include <cuda_runtime.h>
#include <math.h>
#include <cstdint>

// Problem constants
#define DD   2048      // hidden dim
#define EE   64        // experts
#define NTOK 32768     // B*T = 4*8192
#define KTOP 8

// GEMM tiling
#define BM   128       // tokens per block
#define DK   32        // D-chunk staged in smem
#define TPB  256

typedef unsigned long long u64;

// 8 MB scratch for logits (device global: allocation-free per harness rules)
__device__ float g_logits[(size_t)NTOK * EE];

__device__ __forceinline__ u64 pack2(float lo, float hi) {
    u64 r;
    asm("mov.b64 %0, {%1, %2};" : "=l"(r) : "f"(lo), "f"(hi));
    return r;
}
__device__ __forceinline__ void unpack2(u64 p, float& lo, float& hi) {
    asm("mov.b64 {%0, %1}, %2;" : "=f"(lo), "=f"(hi) : "l"(p));
}
__device__ __forceinline__ void fma2(u64& acc, u64 a, u64 b) {
    // Blackwell packed fp32x2 FMA (products fused, per-component .rn)
    asm("fma.rn.f32x2 %0, %1, %2, %0;" : "+l"(acc) : "l"(a), "l"(b));
}
__device__ __forceinline__ u64 add2(u64 a, u64 b) {
    u64 r;
    asm("add.rn.f32x2 %0, %1, %2;" : "=l"(r) : "l"(a), "l"(b));
    return r;
}
// packed negate via sign-bit flip (opaque to FP reassociation)
#define NEG2(x) ((x) ^ 0x8000000080000000ULL)

// ---------------------------------------------------------------------------
// Kernel 1: logits[t][e] = sum_d x[t][d] * w[d][e], near-exactly.
//
// Per-thread microtile: 4 tokens x 8 experts, accumulators packed along the
// EXPERT dim (so the B operand is a direct u64 load from smem, no dup).
// Accuracy: chunk-8 fresh inner accumulator p (inner rounding ~5e-8 total),
// folded into running sum s with fast2Sum; fold errors collected in Neumaier
// compensation c (outer error ~eps^2). Final logit = s + c.
// Total logit error ~5.5e-8 (<= half an fp32 ulp of the result), so fp32
// softmax probabilities collide bitwise exactly where the true values do --
// matching the reference's top_k tie behavior on near-degenerate pairs.
// ---------------------------------------------------------------------------
__global__ __launch_bounds__(TPB, 1)
void router_gemm(const float* __restrict__ x, const float* __restrict__ w) {
    __shared__ float xs[DK][BM];   // x chunk transposed: [d][token]  (16 KB)
    __shared__ float ws[DK][EE];   // w chunk: [d][expert]            (8 KB)

    const int tid = threadIdx.x;
    const int tx  = tid & 7;       // expert octet: experts tx*8 .. tx*8+7
    const int ty  = tid >> 3;      // token quad:   tokens  ty*4 .. ty*4+3
    const int tokBase = blockIdx.x * BM;

    // s/c[t][j]: token ty*4+t, experts (tx*8+2j, tx*8+2j+1) packed
    u64 s[4][4], c[4][4];
#pragma unroll
    for (int t = 0; t < 4; t++)
#pragma unroll
        for (int j = 0; j < 4; j++) { s[t][j] = 0ull; c[t][j] = 0ull; }

    // x staging: thread -> row r, half h (16 d-values)
    const int r = tid >> 1;
    const int h = tid & 1;
    const float* xptr = x + (size_t)(tokBase + r) * DD + h * 16;

    // prologue: prefetch chunk 0
    float4 rx[4], rw[2];
    {
        const float4* xg = (const float4*)xptr;
#pragma unroll
        for (int i = 0; i < 4; i++) rx[i] = xg[i];
        const float4* wg = (const float4*)w;   // chunk contiguous: w + ch*DK*EE
        rw[0] = wg[tid * 2];
        rw[1] = wg[tid * 2 + 1];
    }

    const int NCHUNK = DD / DK;   // 64
    for (int ch = 0; ch < NCHUNK; ch++) {
        __syncthreads();
        // stage x transposed: xs[d][token]
#pragma unroll
        for (int k = 0; k < 4; k++) {
            xs[h * 16 + k * 4 + 0][r] = rx[k].x;
            xs[h * 16 + k * 4 + 1][r] = rx[k].y;
            xs[h * 16 + k * 4 + 2][r] = rx[k].z;
            xs[h * 16 + k * 4 + 3][r] = rx[k].w;
        }
        // stage w (straight copy, layout matches)
        {
            float4* wsp = (float4*)&ws[0][0];
            wsp[tid * 2]     = rw[0];
            wsp[tid * 2 + 1] = rw[1];
        }
        // prefetch next chunk (hidden under compute)
        if (ch + 1 < NCHUNK) {
            const float4* xg = (const float4*)(xptr + (ch + 1) * DK);
#pragma unroll
            for (int i = 0; i < 4; i++) rx[i] = xg[i];
            const float4* wg = (const float4*)(w + (size_t)(ch + 1) * DK * EE);
            rw[0] = wg[tid * 2];
            rw[1] = wg[tid * 2 + 1];
        }
        __syncthreads();

#pragma unroll
        for (int sub = 0; sub < 4; sub++) {
            // fresh 8-term inner accumulator
            u64 p[4][4];
#pragma unroll
            for (int t = 0; t < 4; t++)
#pragma unroll
                for (int j = 0; j < 4; j++) p[t][j] = 0ull;

#pragma unroll
            for (int dd = 0; dd < 8; dd++) {
                const int d = sub * 8 + dd;
                // a: 4 token values (broadcast across tx), dup-packed
                float4 av = *(const float4*)&xs[d][ty * 4];
                u64 a2[4];
                a2[0] = pack2(av.x, av.x);
                a2[1] = pack2(av.y, av.y);
                a2[2] = pack2(av.z, av.z);
                a2[3] = pack2(av.w, av.w);
                // b: 8 experts = 4 packed pairs, direct loads
                const u64* bp = (const u64*)&ws[d][tx * 8];
                u64 bb[4];
                bb[0] = bp[0]; bb[1] = bp[1]; bb[2] = bp[2]; bb[3] = bp[3];

#pragma unroll
                for (int t = 0; t < 4; t++)
#pragma unroll
                    for (int j = 0; j < 4; j++)
                        fma2(p[t][j], a2[t], bb[j]);
            }

            // fast2Sum fold: s_new = s + p exactly split; err -> c (Neumaier)
#pragma unroll
            for (int t = 0; t < 4; t++)
#pragma unroll
                for (int j = 0; j < 4; j++) {
                    const u64 sv = s[t][j];
                    const u64 pv = p[t][j];
                    const u64 tt = add2(sv, pv);
                    const u64 e  = add2(add2(sv, NEG2(tt)), pv);  // (s - t) + p
                    s[t][j] = tt;
                    c[t][j] = add2(c[t][j], e);
                }
        }
    }

    // logits = s + c; write to scratch
#pragma unroll
    for (int t = 0; t < 4; t++) {
        float v[8];
#pragma unroll
        for (int j = 0; j < 4; j++) {
            const u64 f = add2(s[t][j], c[t][j]);
            unpack2(f, v[2 * j], v[2 * j + 1]);
        }
        const int tok = tokBase + ty * 4 + t;
        float4* o = (float4*)&g_logits[(size_t)tok * EE + tx * 8];
        o[0] = make_float4(v[0], v[1], v[2], v[3]);
        o[1] = make_float4(v[4], v[5], v[6], v[7]);
    }
}

// ---------------------------------------------------------------------------
// Kernel 2: per-token softmax(64) -> top-8 ranked on fp32 PROBABILITIES
// (bitwise ties -> lower index, matching jax.lax.top_k over softmax output)
// -> softmax(8). One warp per token, 2 values per lane.
// ---------------------------------------------------------------------------
__global__ __launch_bounds__(256)
void router_topk(float* __restrict__ outw, float* __restrict__ outi) {
    const int warp = (blockIdx.x * blockDim.x + threadIdx.x) >> 5;
    const int lane = threadIdx.x & 31;
    if (warp >= NTOK) return;

    const float* lg = g_logits + (size_t)warp * EE;
    const float k0 = lg[lane];
    const float k1 = lg[lane + 32];

    // softmax over 64 in fp32 (accurate expf + IEEE div, same formula as ref)
    float m = fmaxf(k0, k1);
#pragma unroll
    for (int off = 16; off; off >>= 1) m = fmaxf(m, __shfl_xor_sync(0xffffffffu, m, off));
    const float e0 = expf(k0 - m);
    const float e1 = expf(k1 - m);
    float ssum = e0 + e1;
#pragma unroll
    for (int off = 16; off; off >>= 1) ssum += __shfl_xor_sync(0xffffffffu, ssum, off);
    const float p0 = e0 / ssum;
    const float p1 = e1 / ssum;

    // top-8 on probabilities, lexicographic (value desc, index asc)
    float v0 = p0, v1 = p1;
    float selp = 0.f;
    int   seli = 0;

#pragma unroll
    for (int rr = 0; rr < KTOP; rr++) {
        float bv = v0;
        int   bi = lane;
        if (v1 > bv) { bv = v1; bi = lane + 32; }  // tie keeps lower index
#pragma unroll
        for (int off = 16; off; off >>= 1) {
            float ov = __shfl_down_sync(0xffffffffu, bv, off);
            int   oi = __shfl_down_sync(0xffffffffu, bi, off);
            if (ov > bv || (ov == bv && oi < bi)) { bv = ov; bi = oi; }
        }
        bv = __shfl_sync(0xffffffffu, bv, 0);
        bi = __shfl_sync(0xffffffffu, bi, 0);
        if (lane == rr) { selp = bv; seli = bi; }
        if (bi == lane)      v0 = -__int_as_float(0x7f800000);  // -inf
        if (bi == lane + 32) v1 = -__int_as_float(0x7f800000);
    }

    // lanes 0..7 hold top-8 probs (descending): softmax over the 8
    const float pm = __shfl_sync(0xffffffffu, selp, 0);   // max prob (lane 0)
    float e  = expf(selp - pm);
    float es = e;
#pragma unroll
    for (int off = 4; off; off >>= 1) es += __shfl_xor_sync(0xffffffffu, es, off);

    if (lane < KTOP) {
        outw[(size_t)warp * KTOP + lane] = e / es;
        outi[(size_t)warp * KTOP + lane] = (float)seli;
    }
}

// ---------------------------------------------------------------------------
extern "C" void kernel_launch(void* const* d_in, const int* in_sizes, int n_in,
                              void* d_out, int out_size) {
    const float* x = (const float*)d_in[0];   // (4, 8192, 2048) f32
    const float* w = (const float*)d_in[1];   // (2048, 64) f32
    // d_in[2] = num_experts_per_tok (always 8)
    float* out  = (float*)d_out;
    float* outw = out;                          // weights: 32768*8
    float* outi = out + (size_t)NTOK * KTOP;    // indices (as float): 32768*8

    router_gemm<<<NTOK / BM, TPB>>>(x, w);
    router_topk<<<NTOK / 8, 256>>>(outw, outi);
}